// round 13
// baseline (speedup 1.0000x reference)
#include <cuda_runtime.h>

#define H 1024
#define L 256
#define BATCH 64
#define NCTA 128
#define NTH 256
#define IDX_PER_CTA 8
#define FPAD 8                 // flags padded to one per 32B sector
#define TCHUNK 4               // phase-1 parallelism over t

// Scratch (no cudaMalloc allowed).
__device__ float    g_hs[L * H];              // hidden trajectory (batch elem 0)
__device__ unsigned g_flags[L * NCTA * FPAD]; // per-step per-CTA warp-arrival counters
__device__ float    g_gi[L * NCTA * 24];      // gi: [t][cta][gate(3)][warp(8)]
__device__ float    g_dot;                    // accumulated w_out . feat_row

__device__ __forceinline__ float sigmoidf_(float v) {
    return 1.0f / (1.0f + expf(-v));
}

__device__ __forceinline__ float warp_sum(float v) {
    #pragma unroll
    for (int off = 16; off; off >>= 1)
        v += __shfl_xor_sync(0xffffffffu, v, off);
    return v;
}

// Packed dual-FMA (Blackwell f32x2) — PTX-only, ptxas never emits from C++.
__device__ __forceinline__ unsigned long long fma2(unsigned long long a,
                                                   unsigned long long b,
                                                   unsigned long long c) {
    unsigned long long d;
    asm("fma.rn.f32x2 %0, %1, %2, %3;" : "=l"(d) : "l"(a), "l"(b), "l"(c));
    return d;
}
__device__ __forceinline__ float unpack_sum(unsigned long long a) {
    float lo, hi;
    asm("mov.b64 {%0,%1}, %2;" : "=f"(lo), "=f"(hi) : "l"(a));
    return lo + hi;
}

// Acquire poll load / per-warp release-increment through L2.
__device__ __forceinline__ unsigned ld_acq(const unsigned* p) {
    unsigned v;
    asm volatile("ld.global.acquire.gpu.u32 %0, [%1];" : "=r"(v) : "l"(p) : "memory");
    return v;
}
__device__ __forceinline__ void red_rel_add(unsigned* p, unsigned v) {
    asm volatile("red.release.gpu.global.add.u32 [%0], %1;" :: "l"(p), "r"(v) : "memory");
}

__global__ void init_kernel() {
    int i = blockIdx.x * blockDim.x + threadIdx.x;
    if (i < L * NCTA * FPAD) g_flags[i] = 0u;
    if (i == 0) g_dot = 0.f;
}

__device__ __forceinline__ int detect_stride(const int* x32) {
    // int64 tokens -> odd int32 words all zero
    int odd_all_zero = 1;
    #pragma unroll
    for (int k = 0; k < 8; k++)
        if (x32[2 * k + 1] != 0) odd_all_zero = 0;
    return odd_all_zero ? 2 : 1;
}

// ===== Phase 1: gi[t] = e_t @ W_ih^T (+ folded biases); parallel over t =====
__global__ void __launch_bounds__(NTH, 2) gates_kernel(
    const int* __restrict__ x32,
    const float* __restrict__ emb,
    const float* __restrict__ w_ih,
    const float* __restrict__ b_ih,
    const float* __restrict__ b_hh)
{
    __shared__ float4 e_s4[H / 4];

    const int tid = threadIdx.x;
    const int w   = tid >> 5;
    const int l   = tid & 31;
    const int cta = blockIdx.x;
    const int j   = cta * IDX_PER_CTA + w;
    const int t0  = blockIdx.y * (L / TCHUNK);
    const int t1  = t0 + (L / TCHUNK);

    const int stride = detect_stride(x32);

    float gib0 = 0.f, gib1 = 0.f, gib2 = 0.f;
    if (l == 0) {
        gib0 = b_ih[j]         + b_hh[j];
        gib1 = b_ih[H + j]     + b_hh[H + j];
        gib2 = b_ih[2 * H + j];
    }

    ulonglong2 wr0[8], wr1[8], wr2[8];
    {
        const float* base = w_ih + (size_t)j * H + l * 4;
        #pragma unroll
        for (int k = 0; k < 8; k++) {
            wr0[k] = *(const ulonglong2*)(base + k * 128);
            wr1[k] = *(const ulonglong2*)(base + (size_t)H * H + k * 128);
            wr2[k] = *(const ulonglong2*)(base + (size_t)2 * H * H + k * 128);
        }
    }
    const ulonglong2* e_p2 = (const ulonglong2*)e_s4;

    {
        int tok0 = x32[(size_t)t0 * BATCH * stride];
        float4 cur = *(const float4*)(emb + (size_t)tok0 * H + tid * 4);
        for (int t = t0; t < t1; t++) {
            e_s4[tid] = cur;
            __syncthreads();
            float4 nxt = make_float4(0.f, 0.f, 0.f, 0.f);
            if (t + 1 < t1) {
                int tk = x32[(size_t)(t + 1) * BATCH * stride];
                nxt = *(const float4*)(emb + (size_t)tk * H + tid * 4);
            }
            unsigned long long a0 = 0, a1 = 0, a2 = 0;
            #pragma unroll
            for (int k = 0; k < 8; k++) {
                ulonglong2 ee = e_p2[k * 32 + l];
                a0 = fma2(wr0[k].x, ee.x, a0); a0 = fma2(wr0[k].y, ee.y, a0);
                a1 = fma2(wr1[k].x, ee.x, a1); a1 = fma2(wr1[k].y, ee.y, a1);
                a2 = fma2(wr2[k].x, ee.x, a2); a2 = fma2(wr2[k].y, ee.y, a2);
            }
            float s0 = warp_sum(unpack_sum(a0));
            float s1 = warp_sum(unpack_sum(a1));
            float s2 = warp_sum(unpack_sum(a2));
            if (l == 0) {
                float* gi = &g_gi[((size_t)t * NCTA + cta) * 24];
                gi[w]      = s0 + gib0;
                gi[8 + w]  = s1 + gib1;
                gi[16 + w] = s2 + gib2;
            }
            __syncthreads();
            cur = nxt;
        }
    }
}

// ===== Phase 2: recurrence. Warp0 poll + one barrier; register-direct h; =====
// ===== per-warp publish + red.release counter (flag counts to 8).       =====
__global__ void __launch_bounds__(NTH, 1) rec_kernel(
    const float* __restrict__ w_hh,
    const float* __restrict__ b_hh,
    const float* __restrict__ w_out)
{
    __shared__ float dotbuf[8];

    const int tid = threadIdx.x;
    const int w   = tid >> 5;
    const int l   = tid & 31;
    const int cta = blockIdx.x;
    const int j   = cta * IDX_PER_CTA + w;

    float bhn = 0.f;
    if (l == 0) bhn = b_hh[2 * H + j];

    ulonglong2 wr0[8], wr1[8], wr2[8];
    {
        const float* base = w_hh + (size_t)j * H + l * 4;
        #pragma unroll
        for (int k = 0; k < 8; k++) {
            wr0[k] = *(const ulonglong2*)(base + k * 128);
            wr1[k] = *(const ulonglong2*)(base + (size_t)H * H + k * 128);
            wr2[k] = *(const ulonglong2*)(base + (size_t)2 * H * H + k * 128);
        }
    }

    float dot_local = 0.f;
    float h_prev = 0.f;     // lane0: this warp's own h_{t-1}[j], carried in-register

    for (int t = 0; t < L; t++) {
        // off-chain prefetches (h-independent)
        float gi0 = 0.f, gi1 = 0.f, gi2 = 0.f, wo = 0.f;
        if (l == 0) {
            const float* gi = &g_gi[((size_t)t * NCTA + cta) * 24];
            gi0 = __ldcg(gi + w);
            gi1 = __ldcg(gi + 8 + w);
            gi2 = __ldcg(gi + 16 + w);
            wo  = __ldg(&w_out[(size_t)t * H + j]);
        }

        float s0 = 0.f, s1 = 0.f, s2 = 0.f;
        if (t > 0) {
            if (tid < 32) {   // warp 0: bounded hot spin; each flag counts to 8
                const unsigned* fb = &g_flags[(size_t)(t - 1) * NCTA * FPAD];
                int spins = 0;
                for (;;) {
                    unsigned a0 = ld_acq(fb + (tid)      * FPAD);
                    unsigned a1 = ld_acq(fb + (tid + 32) * FPAD);
                    unsigned a2 = ld_acq(fb + (tid + 64) * FPAD);
                    unsigned a3 = ld_acq(fb + (tid + 96) * FPAD);
                    // AND of values in [0,8] equals 8 iff all are 8
                    if (__all_sync(0xffffffffu, (a0 & a1 & a2 & a3) == 8u)) break;
                    if (++spins > 4096) __nanosleep(32);   // safety backoff only
                }
            }
            __syncthreads();   // broadcasts warp0's acquire to all warps

            // Direct register loads of this lane's fma slice of h_{t-1}.
            // First warp misses to L2; warps 2..8 hit L1 (line flushed per
            // launch, first touch is this step -> no stale-line hazard).
            const float* hrow = g_hs + (size_t)(t - 1) * H + l * 4;
            ulonglong2 hh[8];
            #pragma unroll
            for (int k = 0; k < 8; k++)
                hh[k] = *(const ulonglong2*)(hrow + k * 128);

            unsigned long long a0 = 0, a1 = 0, a2 = 0;
            #pragma unroll
            for (int k = 0; k < 8; k++) {
                a0 = fma2(wr0[k].x, hh[k].x, a0); a0 = fma2(wr0[k].y, hh[k].y, a0);
                a1 = fma2(wr1[k].x, hh[k].x, a1); a1 = fma2(wr1[k].y, hh[k].y, a1);
                a2 = fma2(wr2[k].x, hh[k].x, a2); a2 = fma2(wr2[k].y, hh[k].y, a2);
            }
            s0 = warp_sum(unpack_sum(a0));
            s1 = warp_sum(unpack_sum(a1));
            s2 = warp_sum(unpack_sum(a2));
        }

        float h2 = 0.f;
        if (l == 0) {
            float r  = sigmoidf_(gi0 + s0);
            float z  = sigmoidf_(gi1 + s1);
            float n  = tanhf(gi2 + r * (s2 + bhn));
            h2 = z * (h_prev - n) + n;
            h_prev = h2;
            g_hs[(size_t)t * H + j] = h2;                              // publish
            red_rel_add(&g_flags[((size_t)t * NCTA + cta) * FPAD], 1u); // arrive
            dot_local = fmaf(wo, h2, dot_local);   // off-chain bookkeeping
        }
    }

    // one atomic per CTA for the output dot
    if (l == 0) dotbuf[w] = dot_local;
    __syncthreads();
    if (tid == 0) {
        float s = 0.f;
        #pragma unroll
        for (int k = 0; k < 8; k++) s += dotbuf[k];
        atomicAdd(&g_dot, s);
    }
}

// feat[b, :] = g_hs (64 identical rows) — pure bandwidth.
__global__ void feat_bcast_kernel(float* __restrict__ out) {
    size_t i = (size_t)blockIdx.x * blockDim.x + threadIdx.x;
    const float4* src = (const float4*)g_hs;
    ((float4*)out)[i] = src[i & (size_t)(L * H / 4 - 1)];
}

__global__ void finalize_kernel(const float* __restrict__ b_out,
                                float* __restrict__ out) {
    float v = 1.0f / (1.0f + expf(-(g_dot + b_out[0])));
    if (threadIdx.x < BATCH) out[threadIdx.x] = v;
}

extern "C" void kernel_launch(void* const* d_in, const int* in_sizes, int n_in,
                              void* d_out, int out_size) {
    const int*   x     = (const int*)d_in[0];
    const float* emb   = (const float*)d_in[1];
    const float* w_ih  = (const float*)d_in[2];
    const float* w_hh  = (const float*)d_in[3];
    const float* b_ih  = (const float*)d_in[4];
    const float* b_hh  = (const float*)d_in[5];
    const float* w_out = (const float*)d_in[6];
    const float* b_out = (const float*)d_in[7];
    float* out = (float*)d_out;
    (void)in_sizes; (void)n_in;

    init_kernel<<<(L * NCTA * FPAD + 255) / 256, 256>>>();
    dim3 ggrid(NCTA, TCHUNK);
    gates_kernel<<<ggrid, NTH>>>(x, emb, w_ih, b_ih, b_hh);
    rec_kernel<<<NCTA, NTH>>>(w_hh, b_hh, w_out);

    const size_t BLH = (size_t)BATCH * L * H;   // 16,777,216
    if ((size_t)out_size >= BLH) {
        feat_bcast_kernel<<<(unsigned)(BLH / 4 / 256), 256>>>(out);
        if ((size_t)out_size >= BLH + BATCH)
            finalize_kernel<<<1, 64>>>(b_out, out + BLH);
    } else {
        finalize_kernel<<<1, 64>>>(b_out, out);
    }
}

// round 14
// speedup vs baseline: 1.2720x; 1.2720x over previous
#include <cuda_runtime.h>

#define H 1024
#define L 256
#define BATCH 64
#define NCTA 128
#define NTH 256
#define IDX_PER_CTA 8
#define FPAD 8                 // flags padded to one per 32B sector
#define TCHUNK 4               // phase-1 parallelism over t

// Scratch (no cudaMalloc allowed).
__device__ float    g_hs[L * H];              // hidden trajectory (batch elem 0)
__device__ unsigned g_flags[L * NCTA * FPAD]; // padded per-step per-CTA flags
__device__ float    g_gi[L * NCTA * 24];      // gi: [t][cta][gate(3)][warp(8)]
__device__ float    g_dot;                    // accumulated w_out . feat_row

__device__ __forceinline__ float sigmoidf_(float v) {
    return 1.0f / (1.0f + expf(-v));
}

__device__ __forceinline__ float warp_sum(float v) {
    #pragma unroll
    for (int off = 16; off; off >>= 1)
        v += __shfl_xor_sync(0xffffffffu, v, off);
    return v;
}

// Packed dual-FMA (Blackwell f32x2) — PTX-only, ptxas never emits from C++.
__device__ __forceinline__ unsigned long long fma2(unsigned long long a,
                                                   unsigned long long b,
                                                   unsigned long long c) {
    unsigned long long d;
    asm("fma.rn.f32x2 %0, %1, %2, %3;" : "=l"(d) : "l"(a), "l"(b), "l"(c));
    return d;
}
__device__ __forceinline__ float unpack_sum(unsigned long long a) {
    float lo, hi;
    asm("mov.b64 {%0,%1}, %2;" : "=f"(lo), "=f"(hi) : "l"(a));
    return lo + hi;
}

// Relaxed poll load (parallel-issuable) + release store + post-detect fence.
__device__ __forceinline__ unsigned ld_rlx(const unsigned* p) {
    unsigned v;
    asm volatile("ld.relaxed.gpu.global.u32 %0, [%1];" : "=r"(v) : "l"(p) : "memory");
    return v;
}
__device__ __forceinline__ void st_rel(unsigned* p, unsigned v) {
    asm volatile("st.global.release.gpu.u32 [%0], %1;" :: "l"(p), "r"(v) : "memory");
}
__device__ __forceinline__ void fence_acq() {
    asm volatile("fence.acq_rel.gpu;" ::: "memory");
}

__global__ void init_kernel() {
    int i = blockIdx.x * blockDim.x + threadIdx.x;
    if (i < L * NCTA * FPAD) g_flags[i] = 0u;
    if (i == 0) g_dot = 0.f;
}

__device__ __forceinline__ int detect_stride(const int* x32) {
    // int64 tokens -> odd int32 words all zero
    int odd_all_zero = 1;
    #pragma unroll
    for (int k = 0; k < 8; k++)
        if (x32[2 * k + 1] != 0) odd_all_zero = 0;
    return odd_all_zero ? 2 : 1;
}

// ===== Phase 1: gi[t] = e_t @ W_ih^T (+ folded biases); parallel over t =====
__global__ void __launch_bounds__(NTH, 2) gates_kernel(
    const int* __restrict__ x32,
    const float* __restrict__ emb,
    const float* __restrict__ w_ih,
    const float* __restrict__ b_ih,
    const float* __restrict__ b_hh)
{
    __shared__ float4 e_s4[H / 4];

    const int tid = threadIdx.x;
    const int w   = tid >> 5;
    const int l   = tid & 31;
    const int cta = blockIdx.x;
    const int j   = cta * IDX_PER_CTA + w;
    const int t0  = blockIdx.y * (L / TCHUNK);
    const int t1  = t0 + (L / TCHUNK);

    const int stride = detect_stride(x32);

    float gib0 = 0.f, gib1 = 0.f, gib2 = 0.f;
    if (l == 0) {
        gib0 = b_ih[j]         + b_hh[j];
        gib1 = b_ih[H + j]     + b_hh[H + j];
        gib2 = b_ih[2 * H + j];
    }

    ulonglong2 wr0[8], wr1[8], wr2[8];
    {
        const float* base = w_ih + (size_t)j * H + l * 4;
        #pragma unroll
        for (int k = 0; k < 8; k++) {
            wr0[k] = *(const ulonglong2*)(base + k * 128);
            wr1[k] = *(const ulonglong2*)(base + (size_t)H * H + k * 128);
            wr2[k] = *(const ulonglong2*)(base + (size_t)2 * H * H + k * 128);
        }
    }
    const ulonglong2* e_p2 = (const ulonglong2*)e_s4;

    {
        int tok0 = x32[(size_t)t0 * BATCH * stride];
        float4 cur = *(const float4*)(emb + (size_t)tok0 * H + tid * 4);
        for (int t = t0; t < t1; t++) {
            e_s4[tid] = cur;
            __syncthreads();
            float4 nxt = make_float4(0.f, 0.f, 0.f, 0.f);
            if (t + 1 < t1) {
                int tk = x32[(size_t)(t + 1) * BATCH * stride];
                nxt = *(const float4*)(emb + (size_t)tk * H + tid * 4);
            }
            unsigned long long a0 = 0, a1 = 0, a2 = 0;
            #pragma unroll
            for (int k = 0; k < 8; k++) {
                ulonglong2 ee = e_p2[k * 32 + l];
                a0 = fma2(wr0[k].x, ee.x, a0); a0 = fma2(wr0[k].y, ee.y, a0);
                a1 = fma2(wr1[k].x, ee.x, a1); a1 = fma2(wr1[k].y, ee.y, a1);
                a2 = fma2(wr2[k].x, ee.x, a2); a2 = fma2(wr2[k].y, ee.y, a2);
            }
            float s0 = warp_sum(unpack_sum(a0));
            float s1 = warp_sum(unpack_sum(a1));
            float s2 = warp_sum(unpack_sum(a2));
            if (l == 0) {
                float* gi = &g_gi[((size_t)t * NCTA + cta) * 24];
                gi[w]      = s0 + gib0;
                gi[8 + w]  = s1 + gib1;
                gi[16 + w] = s2 + gib2;
            }
            __syncthreads();
            cur = nxt;
        }
    }
}

// ===== Phase 2: recurrence. R11 structure; poll = relaxed loads + one fence =====
__global__ void __launch_bounds__(NTH, 1) rec_kernel(
    const float* __restrict__ w_hh,
    const float* __restrict__ b_hh,
    const float* __restrict__ w_out)
{
    __shared__ float4 h_s4[H / 4];
    __shared__ float  dotbuf[8];

    const int tid = threadIdx.x;
    const int w   = tid >> 5;
    const int l   = tid & 31;
    const int cta = blockIdx.x;
    const int j   = cta * IDX_PER_CTA + w;
    const float* h_s = (const float*)h_s4;
    const ulonglong2* h_p2 = (const ulonglong2*)h_s4;

    float bhn = 0.f;
    if (l == 0) bhn = b_hh[2 * H + j];

    ulonglong2 wr0[8], wr1[8], wr2[8];
    {
        const float* base = w_hh + (size_t)j * H + l * 4;
        #pragma unroll
        for (int k = 0; k < 8; k++) {
            wr0[k] = *(const ulonglong2*)(base + k * 128);
            wr1[k] = *(const ulonglong2*)(base + (size_t)H * H + k * 128);
            wr2[k] = *(const ulonglong2*)(base + (size_t)2 * H * H + k * 128);
        }
    }

    float dot_local = 0.f;

    for (int t = 0; t < L; t++) {
        // off-chain prefetches (h-independent)
        float gi0 = 0.f, gi1 = 0.f, gi2 = 0.f, wo = 0.f;
        if (l == 0) {
            const float* gi = &g_gi[((size_t)t * NCTA + cta) * 24];
            gi0 = __ldcg(gi + w);
            gi1 = __ldcg(gi + 8 + w);
            gi2 = __ldcg(gi + 16 + w);
            wo  = __ldg(&w_out[(size_t)t * H + j]);
        }

        if (t == 0) {
            h_s4[tid] = make_float4(0.f, 0.f, 0.f, 0.f);
            __syncthreads();
        } else {
            if (tid < 32) {   // warp 0: 4 RELAXED loads/iteration (parallel issue)
                const unsigned* fb = &g_flags[(size_t)(t - 1) * NCTA * FPAD];
                int spins = 0;
                for (;;) {
                    unsigned a0 = ld_rlx(fb + (tid)      * FPAD);
                    unsigned a1 = ld_rlx(fb + (tid + 32) * FPAD);
                    unsigned a2 = ld_rlx(fb + (tid + 64) * FPAD);
                    unsigned a3 = ld_rlx(fb + (tid + 96) * FPAD);
                    if (__all_sync(0xffffffffu, (a0 & a1 & a2 & a3) != 0u)) break;
                    if (++spins > 4096) __nanosleep(32);   // safety backoff only
                }
                fence_acq();   // one acquire fence, off the iteration loop
            }
            __syncthreads();   // propagates warp0's acquired visibility CTA-wide
            float4 hv = __ldcg((const float4*)(g_hs + (size_t)(t - 1) * H) + tid);
            h_s4[tid] = hv;
            __syncthreads();
        }

        unsigned long long a0 = 0, a1 = 0, a2 = 0;
        #pragma unroll
        for (int k = 0; k < 8; k++) {
            ulonglong2 hh = h_p2[k * 32 + l];
            a0 = fma2(wr0[k].x, hh.x, a0); a0 = fma2(wr0[k].y, hh.y, a0);
            a1 = fma2(wr1[k].x, hh.x, a1); a1 = fma2(wr1[k].y, hh.y, a1);
            a2 = fma2(wr2[k].x, hh.x, a2); a2 = fma2(wr2[k].y, hh.y, a2);
        }
        float s0 = warp_sum(unpack_sum(a0));
        float s1 = warp_sum(unpack_sum(a1));
        float s2 = warp_sum(unpack_sum(a2));

        float h2 = 0.f;
        if (l == 0) {
            float r  = sigmoidf_(gi0 + s0);
            float z  = sigmoidf_(gi1 + s1);
            float n  = tanhf(gi2 + r * (s2 + bhn));
            float hp = h_s[j];
            h2 = z * (hp - n) + n;
            g_hs[(size_t)t * H + j] = h2;     // direct publish
        }
        __syncthreads();                      // all 8 warps' publishes ordered
        if (tid == 0)
            st_rel(&g_flags[((size_t)t * NCTA + cta) * FPAD], 1u);

        if (l == 0)
            dot_local = fmaf(wo, h2, dot_local);   // off-chain bookkeeping
    }

    // one atomic per CTA for the output dot
    if (l == 0) dotbuf[w] = dot_local;
    __syncthreads();
    if (tid == 0) {
        float s = 0.f;
        #pragma unroll
        for (int k = 0; k < 8; k++) s += dotbuf[k];
        atomicAdd(&g_dot, s);
    }
}

// feat[b, :] = g_hs (64 identical rows) — pure bandwidth.
__global__ void feat_bcast_kernel(float* __restrict__ out) {
    size_t i = (size_t)blockIdx.x * blockDim.x + threadIdx.x;
    const float4* src = (const float4*)g_hs;
    ((float4*)out)[i] = src[i & (size_t)(L * H / 4 - 1)];
}

__global__ void finalize_kernel(const float* __restrict__ b_out,
                                float* __restrict__ out) {
    float v = 1.0f / (1.0f + expf(-(g_dot + b_out[0])));
    if (threadIdx.x < BATCH) out[threadIdx.x] = v;
}

extern "C" void kernel_launch(void* const* d_in, const int* in_sizes, int n_in,
                              void* d_out, int out_size) {
    const int*   x     = (const int*)d_in[0];
    const float* emb   = (const float*)d_in[1];
    const float* w_ih  = (const float*)d_in[2];
    const float* w_hh  = (const float*)d_in[3];
    const float* b_ih  = (const float*)d_in[4];
    const float* b_hh  = (const float*)d_in[5];
    const float* w_out = (const float*)d_in[6];
    const float* b_out = (const float*)d_in[7];
    float* out = (float*)d_out;
    (void)in_sizes; (void)n_in;

    init_kernel<<<(L * NCTA * FPAD + 255) / 256, 256>>>();
    dim3 ggrid(NCTA, TCHUNK);
    gates_kernel<<<ggrid, NTH>>>(x, emb, w_ih, b_ih, b_hh);
    rec_kernel<<<NCTA, NTH>>>(w_hh, b_hh, w_out);

    const size_t BLH = (size_t)BATCH * L * H;   // 16,777,216
    if ((size_t)out_size >= BLH) {
        feat_bcast_kernel<<<(unsigned)(BLH / 4 / 256), 256>>>(out);
        if ((size_t)out_size >= BLH + BATCH)
            finalize_kernel<<<1, 64>>>(b_out, out + BLH);
    } else {
        finalize_kernel<<<1, 64>>>(b_out, out);
    }
}

// round 15
// speedup vs baseline: 1.3759x; 1.0817x over previous
#include <cuda_runtime.h>

#define H 1024
#define L 256
#define BATCH 64
#define NCTA 128
#define NTH 256
#define IDX_PER_CTA 8
#define TCHUNK 4               // phase-1 parallelism over t
#define TOTCH (NCTA * 3)       // 384 chunks per step

// Scratch (no cudaMalloc allowed). All zero-initialized at module load.
__device__ uint4    g_hx[L * TOTCH];     // {h0,h1,h2|tag} 16B self-validating chunks
__device__ float    g_hs[L * H];         // plain trajectory copy (for feat bcast)
__device__ float    g_gi[L * NCTA * 24]; // gi: [t][cta][gate(3)][warp(8)]
__device__ unsigned g_epoch;             // bumped once per kernel_launch
__device__ float    g_dot;               // accumulated w_out . feat_row

__device__ __forceinline__ float sigmoidf_(float v) {
    return 1.0f / (1.0f + expf(-v));
}

__device__ __forceinline__ float warp_sum(float v) {
    #pragma unroll
    for (int off = 16; off; off >>= 1)
        v += __shfl_xor_sync(0xffffffffu, v, off);
    return v;
}

// Packed dual-FMA (Blackwell f32x2) — PTX-only, ptxas never emits from C++.
__device__ __forceinline__ unsigned long long fma2(unsigned long long a,
                                                   unsigned long long b,
                                                   unsigned long long c) {
    unsigned long long d;
    asm("fma.rn.f32x2 %0, %1, %2, %3;" : "=l"(d) : "l"(a), "l"(b), "l"(c));
    return d;
}
__device__ __forceinline__ float unpack_sum(unsigned long long a) {
    float lo, hi;
    asm("mov.b64 {%0,%1}, %2;" : "=f"(lo), "=f"(hi) : "l"(a));
    return lo + hi;
}

// L2-direct integer 16B load/store; volatile so poll loops re-issue.
__device__ __forceinline__ uint4 ldcg_u4(const uint4* p) {
    uint4 v;
    asm volatile("ld.global.cg.v4.u32 {%0,%1,%2,%3}, [%4];"
                 : "=r"(v.x), "=r"(v.y), "=r"(v.z), "=r"(v.w) : "l"(p) : "memory");
    return v;
}
__device__ __forceinline__ void stcg_u4(uint4* p, uint4 v) {
    asm volatile("st.global.cg.v4.u32 [%0], {%1,%2,%3,%4};"
                 :: "l"(p), "r"(v.x), "r"(v.y), "r"(v.z), "r"(v.w) : "memory");
}

__global__ void init_kernel() {
    g_epoch = g_epoch + 1u;   // unique tag space per launch; no 1MB re-init needed
    g_dot = 0.f;
}

__device__ __forceinline__ int detect_stride(const int* x32) {
    // int64 tokens -> odd int32 words all zero
    int odd_all_zero = 1;
    #pragma unroll
    for (int k = 0; k < 8; k++)
        if (x32[2 * k + 1] != 0) odd_all_zero = 0;
    return odd_all_zero ? 2 : 1;
}

// ===== Phase 1: gi[t] = e_t @ W_ih^T (+ folded biases); parallel over t =====
__global__ void __launch_bounds__(NTH, 2) gates_kernel(
    const int* __restrict__ x32,
    const float* __restrict__ emb,
    const float* __restrict__ w_ih,
    const float* __restrict__ b_ih,
    const float* __restrict__ b_hh)
{
    __shared__ float4 e_s4[H / 4];

    const int tid = threadIdx.x;
    const int w   = tid >> 5;
    const int l   = tid & 31;
    const int cta = blockIdx.x;
    const int j   = cta * IDX_PER_CTA + w;
    const int t0  = blockIdx.y * (L / TCHUNK);
    const int t1  = t0 + (L / TCHUNK);

    const int stride = detect_stride(x32);

    float gib0 = 0.f, gib1 = 0.f, gib2 = 0.f;
    if (l == 0) {
        gib0 = b_ih[j]         + b_hh[j];
        gib1 = b_ih[H + j]     + b_hh[H + j];
        gib2 = b_ih[2 * H + j];
    }

    ulonglong2 wr0[8], wr1[8], wr2[8];
    {
        const float* base = w_ih + (size_t)j * H + l * 4;
        #pragma unroll
        for (int k = 0; k < 8; k++) {
            wr0[k] = *(const ulonglong2*)(base + k * 128);
            wr1[k] = *(const ulonglong2*)(base + (size_t)H * H + k * 128);
            wr2[k] = *(const ulonglong2*)(base + (size_t)2 * H * H + k * 128);
        }
    }
    const ulonglong2* e_p2 = (const ulonglong2*)e_s4;

    {
        int tok0 = x32[(size_t)t0 * BATCH * stride];
        float4 cur = *(const float4*)(emb + (size_t)tok0 * H + tid * 4);
        for (int t = t0; t < t1; t++) {
            e_s4[tid] = cur;
            __syncthreads();
            float4 nxt = make_float4(0.f, 0.f, 0.f, 0.f);
            if (t + 1 < t1) {
                int tk = x32[(size_t)(t + 1) * BATCH * stride];
                nxt = *(const float4*)(emb + (size_t)tk * H + tid * 4);
            }
            unsigned long long a0 = 0, a1 = 0, a2 = 0;
            #pragma unroll
            for (int k = 0; k < 8; k++) {
                ulonglong2 ee = e_p2[k * 32 + l];
                a0 = fma2(wr0[k].x, ee.x, a0); a0 = fma2(wr0[k].y, ee.y, a0);
                a1 = fma2(wr1[k].x, ee.x, a1); a1 = fma2(wr1[k].y, ee.y, a1);
                a2 = fma2(wr2[k].x, ee.x, a2); a2 = fma2(wr2[k].y, ee.y, a2);
            }
            float s0 = warp_sum(unpack_sum(a0));
            float s1 = warp_sum(unpack_sum(a1));
            float s2 = warp_sum(unpack_sum(a2));
            if (l == 0) {
                float* gi = &g_gi[((size_t)t * NCTA + cta) * 24];
                gi[w]      = s0 + gib0;
                gi[8 + w]  = s1 + gib1;
                gi[16 + w] = s2 + gib2;
            }
            __syncthreads();
            cur = nxt;
        }
    }
}

// ===== Phase 2: recurrence with epoch-tagged single-load exchange =====
__global__ void __launch_bounds__(NTH, 1) rec_kernel(
    const float* __restrict__ w_hh,
    const float* __restrict__ b_hh,
    const float* __restrict__ w_out)
{
    __shared__ float4 h_s4[H / 4];     // assembled h_{t-1}
    __shared__ float  h2buf[8];
    __shared__ float  dotbuf[8];

    const int tid = threadIdx.x;
    const int w   = tid >> 5;
    const int l   = tid & 31;
    const int cta = blockIdx.x;
    const int j   = cta * IDX_PER_CTA + w;
    float* h_s = (float*)h_s4;
    const ulonglong2* h_p2 = (const ulonglong2*)h_s4;

    const unsigned ebase = g_epoch << 8;   // after init_kernel (stream order)

    // chunk mapping (constant over t): chunk g -> cta g/3, slot g%3
    const int gA = tid;                // chunks 0..255
    const int cA = gA / 3, kA = gA % 3, baseA = cA * 8 + kA * 3;
    const int gB = 256 + tid;          // chunks 256..383 (tid < 128)
    const int cB = gB / 3, kB = gB % 3, baseB = cB * 8 + kB * 3;
    const bool hasB = (tid < TOTCH - 256);

    float bhn = 0.f;
    if (l == 0) bhn = b_hh[2 * H + j];

    ulonglong2 wr0[8], wr1[8], wr2[8];
    {
        const float* base = w_hh + (size_t)j * H + l * 4;
        #pragma unroll
        for (int k = 0; k < 8; k++) {
            wr0[k] = *(const ulonglong2*)(base + k * 128);
            wr1[k] = *(const ulonglong2*)(base + (size_t)H * H + k * 128);
            wr2[k] = *(const ulonglong2*)(base + (size_t)2 * H * H + k * 128);
        }
    }

    float dot_local = 0.f;

    for (int t = 0; t < L; t++) {
        // off-chain prefetches (h-independent)
        float gi0 = 0.f, gi1 = 0.f, gi2 = 0.f, wo = 0.f;
        if (l == 0) {
            const float* gi = &g_gi[((size_t)t * NCTA + cta) * 24];
            gi0 = __ldcg(gi + w);
            gi1 = __ldcg(gi + 8 + w);
            gi2 = __ldcg(gi + 16 + w);
            wo  = __ldg(&w_out[(size_t)t * H + j]);
        }

        if (t == 0) {
            h_s4[tid] = make_float4(0.f, 0.f, 0.f, 0.f);
        } else {
            // Single-load poll: tag validity rides in the same 16B as the data.
            const unsigned etag = ebase | (unsigned)(t - 1);
            const uint4* pb = g_hx + (size_t)(t - 1) * TOTCH;
            uint4 a, b;
            bool okA = false, okB = !hasB;
            int spins = 0;
            for (;;) {
                if (!okA) { a = ldcg_u4(pb + gA); okA = (a.w == etag); }
                if (!okB) { b = ldcg_u4(pb + gB); okB = (b.w == etag); }
                if (okA && okB) break;
                if (++spins > 8192) __nanosleep(32);
                if (spins > (1 << 20)) break;    // escape: fail visibly, not hang
            }
            h_s[baseA]     = __uint_as_float(a.x);
            h_s[baseA + 1] = __uint_as_float(a.y);
            if (kA < 2) h_s[baseA + 2] = __uint_as_float(a.z);
            if (hasB) {
                h_s[baseB]     = __uint_as_float(b.x);
                h_s[baseB + 1] = __uint_as_float(b.y);
                if (kB < 2) h_s[baseB + 2] = __uint_as_float(b.z);
            }
        }
        __syncthreads();   // bar#1: h_s assembled

        unsigned long long a0 = 0, a1 = 0, a2 = 0;
        #pragma unroll
        for (int k = 0; k < 8; k++) {
            ulonglong2 hh = h_p2[k * 32 + l];
            a0 = fma2(wr0[k].x, hh.x, a0); a0 = fma2(wr0[k].y, hh.y, a0);
            a1 = fma2(wr1[k].x, hh.x, a1); a1 = fma2(wr1[k].y, hh.y, a1);
            a2 = fma2(wr2[k].x, hh.x, a2); a2 = fma2(wr2[k].y, hh.y, a2);
        }
        float s0 = warp_sum(unpack_sum(a0));
        float s1 = warp_sum(unpack_sum(a1));
        float s2 = warp_sum(unpack_sum(a2));

        float h2 = 0.f;
        if (l == 0) {
            float r  = sigmoidf_(gi0 + s0);
            float z  = sigmoidf_(gi1 + s1);
            float n  = tanhf(gi2 + r * (s2 + bhn));
            float hp = h_s[j];
            h2 = z * (hp - n) + n;
            h2buf[w] = h2;
            g_hs[(size_t)t * H + j] = h2;          // plain copy for bcast (off-chain)
            dot_local = fmaf(wo, h2, dot_local);
        }
        __syncthreads();   // bar#2: h2buf complete; also fences h_s reads vs t+1 writes

        if (tid < 3) {     // publish 3 tagged chunks (tag inside each 16B store)
            uint4 c;
            c.x = __float_as_uint(h2buf[tid * 3 + 0]);
            c.y = __float_as_uint(h2buf[tid * 3 + 1]);
            c.z = (tid < 2) ? __float_as_uint(h2buf[tid * 3 + 2]) : 0u;
            c.w = ebase | (unsigned)t;
            stcg_u4(g_hx + (size_t)t * TOTCH + cta * 3 + tid, c);
        }
    }

    // one atomic per CTA for the output dot
    if (l == 0) dotbuf[w] = dot_local;
    __syncthreads();
    if (tid == 0) {
        float s = 0.f;
        #pragma unroll
        for (int k = 0; k < 8; k++) s += dotbuf[k];
        atomicAdd(&g_dot, s);
    }
}

// feat[b, :] = g_hs (64 identical rows) — pure bandwidth.
__global__ void feat_bcast_kernel(float* __restrict__ out) {
    size_t i = (size_t)blockIdx.x * blockDim.x + threadIdx.x;
    const float4* src = (const float4*)g_hs;
    ((float4*)out)[i] = src[i & (size_t)(L * H / 4 - 1)];
}

__global__ void finalize_kernel(const float* __restrict__ b_out,
                                float* __restrict__ out) {
    float v = 1.0f / (1.0f + expf(-(g_dot + b_out[0])));
    if (threadIdx.x < BATCH) out[threadIdx.x] = v;
}

extern "C" void kernel_launch(void* const* d_in, const int* in_sizes, int n_in,
                              void* d_out, int out_size) {
    const int*   x     = (const int*)d_in[0];
    const float* emb   = (const float*)d_in[1];
    const float* w_ih  = (const float*)d_in[2];
    const float* w_hh  = (const float*)d_in[3];
    const float* b_ih  = (const float*)d_in[4];
    const float* b_hh  = (const float*)d_in[5];
    const float* w_out = (const float*)d_in[6];
    const float* b_out = (const float*)d_in[7];
    float* out = (float*)d_out;
    (void)in_sizes; (void)n_in;

    init_kernel<<<1, 1>>>();
    dim3 ggrid(NCTA, TCHUNK);
    gates_kernel<<<ggrid, NTH>>>(x, emb, w_ih, b_ih, b_hh);
    rec_kernel<<<NCTA, NTH>>>(w_hh, b_hh, w_out);

    const size_t BLH = (size_t)BATCH * L * H;   // 16,777,216
    if ((size_t)out_size >= BLH) {
        feat_bcast_kernel<<<(unsigned)(BLH / 4 / 256), 256>>>(out);
        if ((size_t)out_size >= BLH + BATCH)
            finalize_kernel<<<1, 64>>>(b_out, out + BLH);
    } else {
        finalize_kernel<<<1, 64>>>(b_out, out);
    }
}